// round 9
// baseline (speedup 1.0000x reference)
#include <cuda_runtime.h>

#define NF 32
#define RPB 8            // rows per block = warps per block
#define THREADS 256      // 8 warps; ONE row per warp end-to-end

// -----------------------------------------------------------------------------
// out[b,2d]   = (1/32) sum_f sin(x[b,f] w_d)
// out[b,2d+1] = (1/32) sum_f cos(x[b,f] w_d),  w_d = 10^(-d/64), v = w^2
// sin_mean = w * Sum_j A_j v^j,  cos_mean = 1 + v * Sum_j B_{j+1} v^j
//   A_j = S_{2j+1}(-1)^j/((2j+1)! 32),  B_j = S_{2j}(-1)^j/((2j)! 32)
// smem pair k = (A_k, B_{k+1}); ONE f32x2 Horner per d computes both polys.
// Lane covers d = 2*lane, 2*lane+1; step advances d by 64 (v*=0.01, w*=0.1).
// Phase 1: lane owns one x element -> powers are pure muls, no adds.
// -----------------------------------------------------------------------------

typedef unsigned long long u64;

__device__ __forceinline__ u64 pk2(float a, float b) {
    u64 r; asm("mov.b64 %0, {%1, %2};" : "=l"(r) : "f"(a), "f"(b)); return r;
}
__device__ __forceinline__ u64 pmul(u64 a, u64 b) {
    u64 r; asm("mul.rn.f32x2 %0, %1, %2;" : "=l"(r) : "l"(a), "l"(b)); return r;
}
__device__ __forceinline__ u64 pfma(u64 a, u64 b, u64 c) {
    u64 r; asm("fma.rn.f32x2 %0, %1, %2, %3;" : "=l"(r) : "l"(a), "l"(b), "l"(c)); return r;
}
__device__ __forceinline__ void up2(u64 a, float& x, float& y) {
    asm("mov.b64 {%0, %1}, %2;" : "=f"(x), "=f"(y) : "l"(a));
}

#define C32 0.9305720409297f    /* 10^(-1/32) */
#define C64 0.9646616199111f    /* 10^(-1/64) */

__constant__ float KSCALE[24] = {
    // ids 0..11: (-1)^j/((2j+1)! 32)  scales S_{2j+1} -> A_j
    (float)( 1.0 / 32.0),
    (float)(-1.0 / (6.0 * 32.0)),
    (float)( 1.0 / (120.0 * 32.0)),
    (float)(-1.0 / (5040.0 * 32.0)),
    (float)( 1.0 / (362880.0 * 32.0)),
    (float)(-1.0 / (39916800.0 * 32.0)),
    (float)( 1.0 / (6227020800.0 * 32.0)),
    (float)(-1.0 / (1307674368000.0 * 32.0)),
    (float)( 1.0 / (355687428096000.0 * 32.0)),
    (float)(-1.0 / (121645100408832000.0 * 32.0)),
    (float)( 1.0 / (51090942171709440000.0 * 32.0)),
    (float)(-1.0 / (25852016738884976640000.0 * 32.0)),
    // ids 12..23: (-1)^(j+1)/((2j+2)! 32)  scales S_{2j+2} -> B_{j+1}
    (float)(-1.0 / (2.0 * 32.0)),
    (float)( 1.0 / (24.0 * 32.0)),
    (float)(-1.0 / (720.0 * 32.0)),
    (float)( 1.0 / (40320.0 * 32.0)),
    (float)(-1.0 / (3628800.0 * 32.0)),
    (float)( 1.0 / (479001600.0 * 32.0)),
    (float)(-1.0 / (87178291200.0 * 32.0)),
    (float)( 1.0 / (20922789888000.0 * 32.0)),
    (float)(-1.0 / (6402373705728000.0 * 32.0)),
    (float)( 1.0 / (2432902008176640000.0 * 32.0)),
    (float)(-1.0 / (1124000727777607680000.0 * 32.0)),
    (float)( 1.0 / (620448401733239439360000.0 * 32.0))
};

template<int NTERM>
__device__ __forceinline__ u64 horner2(const u64* C, u64 V)
{
    u64 H = C[NTERM - 1];
#pragma unroll
    for (int j = NTERM - 2; j >= 0; --j) H = pfma(V, H, C[j]);
    return H;
}

__global__ void __launch_bounds__(THREADS, 4)   // allow ~64 regs: NO spills
pe_kernel(const float* __restrict__ x, float4* __restrict__ out)
{
    // per-row interleaved coef: float[2k] = A_k, float[2k+1] = B_{k+1}
    __shared__ __align__(16) float scoef[RPB][24];

    const int tid  = threadIdx.x;
    const int wrp  = tid >> 5;               // row in block
    const int lane = tid & 31;
    const int row  = blockIdx.x * RPB + wrp;

    // ===== Phase 1: 32 threads/row, one element each -> pure power chain =====
    {
        const float xx = x[row * NF + lane];  // warp reads 128B contiguous
        const float x2 = xx * xx;
        const u64 X2 = pk2(x2, x2);

        // val[0..11] = S_odd partials, val[12..23] = S_even partials
        float val[24];
        {
            u64 T = pk2(xx, x2);              // (x^1, x^2)
            up2(T, val[0], val[12]);
#pragma unroll
            for (int j = 1; j < 12; ++j) {
                T = pmul(T, X2);              // (x^{2j+1}, x^{2j+2})
                up2(T, val[j], val[12 + j]);
            }
        }

        // reduce-scatter over 32 lanes: 12+6+3 scatter + 3+3 butterfly
        const bool b0 = lane & 1;
#pragma unroll
        for (int i = 0; i < 12; ++i) {
            float keep = b0 ? val[i + 12] : val[i];
            float send = b0 ? val[i]      : val[i + 12];
            val[i] = keep + __shfl_xor_sync(0xffffffffu, send, 1);
        }
        const bool b1 = (lane >> 1) & 1;
#pragma unroll
        for (int i = 0; i < 6; ++i) {
            float keep = b1 ? val[i + 6] : val[i];
            float send = b1 ? val[i]     : val[i + 6];
            val[i] = keep + __shfl_xor_sync(0xffffffffu, send, 2);
        }
        const bool b2 = (lane >> 2) & 1;
#pragma unroll
        for (int i = 0; i < 3; ++i) {
            float keep = b2 ? val[i + 3] : val[i];
            float send = b2 ? val[i]     : val[i + 3];
            val[i] = keep + __shfl_xor_sync(0xffffffffu, send, 4);
        }
#pragma unroll
        for (int i = 0; i < 3; ++i)
            val[i] += __shfl_xor_sync(0xffffffffu, val[i], 8);
#pragma unroll
        for (int i = 0; i < 3; ++i)
            val[i] += __shfl_xor_sync(0xffffffffu, val[i], 16);

        // lanes 0..7 hold distinct id-triples (base..base+2): scale + 3 STS
        if (lane < 8) {
            const int base = 12 * (int)b0 + 6 * (int)b1 + 3 * (int)b2;
            // id<12 (A_k) -> slot 2*id ; id>=12 (B_{k+1}) -> slot 2*(id-12)+1
            const int soff = (base < 12) ? (2 * base) : (2 * base - 23);
#pragma unroll
            for (int i = 0; i < 3; ++i)
                scoef[wrp][soff + 2 * i] = val[i] * KSCALE[base + i];
        }
    }
    __syncwarp();   // warp-local handoff (producer == consumer warp)

    // ===== Phase 2: packed sin/cos Horner, one row per warp =====
    {
        const float wa0 = exp2f((float)lane * -0.10381025296523007f); // 10^(-2l/64)
        const float va0 = exp2f((float)lane * -0.20762050593046014f); // 10^(-2l/32)
        const float vb0 = va0 * C32;
        const float wb0 = wa0 * C64;

        // 6x LDS.128 broadcast, pair into u64 (register aliasing)
        const float4* Cf = (const float4*)scoef[wrp];
        u64 C[12];
#pragma unroll
        for (int q = 0; q < 6; ++q) {
            float4 c = Cf[q];
            C[2 * q]     = pk2(c.x, c.y);
            C[2 * q + 1] = pk2(c.z, c.w);
        }

        u64 Va = pk2(va0, va0), Vb = pk2(vb0, vb0);
        const u64 DEC = pk2(0.01f, 0.01f);
        float wa = wa0, wb = wb0, va = va0, vb = vb0;
        float4* o = out + row * 128 + lane;

        // step 1: d in [0,64), deg 12/13 (|t| <= 5.8)
        {
            u64 Ha = horner2<12>(C, Va);
            u64 Hb = horner2<12>(C, Vb);
            float sa, ca, sb, cb;
            up2(Ha, sa, ca); up2(Hb, sb, cb);
            o[0] = make_float4(wa * sa, fmaf(va, ca, 1.0f),
                               wb * sb, fmaf(vb, cb, 1.0f));
        }
        Va = pmul(Va, DEC); Vb = pmul(Vb, DEC);
        va *= 0.01f; vb *= 0.01f; wa *= 0.1f; wb *= 0.1f;

        // step 2: d in [64,128) (|t| <= 0.58)
        {
            u64 Ha = horner2<4>(C, Va);
            u64 Hb = horner2<4>(C, Vb);
            float sa, ca, sb, cb;
            up2(Ha, sa, ca); up2(Hb, sb, cb);
            o[32] = make_float4(wa * sa, fmaf(va, ca, 1.0f),
                                wb * sb, fmaf(vb, cb, 1.0f));
        }
        Va = pmul(Va, DEC); Vb = pmul(Vb, DEC);
        va *= 0.01f; vb *= 0.01f; wa *= 0.1f; wb *= 0.1f;

        // step 3: d in [128,192) (|t| <= 0.058)
        {
            u64 Ha = horner2<2>(C, Va);
            u64 Hb = horner2<2>(C, Vb);
            float sa, ca, sb, cb;
            up2(Ha, sa, ca); up2(Hb, sb, cb);
            o[64] = make_float4(wa * sa, fmaf(va, ca, 1.0f),
                                wb * sb, fmaf(vb, cb, 1.0f));
        }
        Va = pmul(Va, DEC); Vb = pmul(Vb, DEC);
        va *= 0.01f; vb *= 0.01f; wa *= 0.1f; wb *= 0.1f;

        // step 4: d in [192,256)
        {
            u64 Ha = horner2<2>(C, Va);
            u64 Hb = horner2<2>(C, Vb);
            float sa, ca, sb, cb;
            up2(Ha, sa, ca); up2(Hb, sb, cb);
            o[96] = make_float4(wa * sa, fmaf(va, ca, 1.0f),
                                wb * sb, fmaf(vb, cb, 1.0f));
        }
    }
}

extern "C" void kernel_launch(void* const* d_in, const int* in_sizes, int n_in,
                              void* d_out, int out_size)
{
    const float* x = (const float*)d_in[0];
    float4* out = (float4*)d_out;
    int rows = in_sizes[0] / NF;                 // 16384
    pe_kernel<<<rows / RPB, THREADS>>>(x, out);
}